// round 15
// baseline (speedup 1.0000x reference)
#include <cuda_runtime.h>
#include <math.h>

// Problem constants
#define PN 400
#define PD 512
#define PC 1000
#define PM 16000
#define ALPHA 1.0f
#define BETA 5.5f
#define GAMMA 5.0f

// ---------------- device scratch (no cudaMalloc allowed) ----------------
static __device__ float g_tn[PC * PD];         // normalized text  [C,D]
static __device__ float g_img[PN * PD];        // normalized image [N,D]
static __device__ float g_raw[PN * PC];        // raw dot img@tf  [N,C]
static __device__ float g_p[PN * PC];          // softmax probs   [N,C]
static __device__ float g_ent[PN];             // sum p log p per row
static __device__ float g_TL[(size_t)PM * PC]; // train logits [M,C] (=2*dot)
static __device__ float g_mx[PM];              // row max of TL
static __device__ float g_lsh[PM];             // log sum exp(TL - mx)
static __device__ float g_kl[(size_t)PN * PM];
static __device__ float g_nk[(size_t)PN * PM];
static __device__ float g_minmax[4];           // klmin, klmax, nkmin, nkmax

// ---------------- helpers ----------------
// XLA-GPU-style warp tree reduce (bit-load-bearing: do not change).
__device__ __forceinline__ float warpTreeSum(float v) {
#pragma unroll
    for (int o = 16; o; o >>= 1)
        v = __fadd_rn(v, __shfl_down_sync(0xffffffffu, v, o));
    return v;
}
__device__ __forceinline__ float warpTreeMax(float v) {
#pragma unroll
    for (int o = 16; o; o >>= 1)
        v = fmaxf(v, __shfl_down_sync(0xffffffffu, v, o));
    return v;
}
__device__ __forceinline__ float warpMaxAll(float v) {
#pragma unroll
    for (int o = 16; o; o >>= 1) v = fmaxf(v, __shfl_xor_sync(0xffffffffu, v, o));
    return v;
}
__device__ __forceinline__ float warpMinAll(float v) {
#pragma unroll
    for (int o = 16; o; o >>= 1) v = fminf(v, __shfl_xor_sync(0xffffffffu, v, o));
    return v;
}
__device__ void atomicMaxF(float* address, float val) {
    int* ai = (int*)address;
    int old = *ai;
    while (__int_as_float(old) < val) {
        int assumed = old;
        old = atomicCAS(ai, assumed, __float_as_int(val));
        if (old == assumed) break;
    }
}
__device__ void atomicMinF(float* address, float val) {
    int* ai = (int*)address;
    int old = *ai;
    while (__int_as_float(old) > val) {
        int assumed = old;
        old = atomicCAS(ai, assumed, __float_as_int(val));
        if (old == assumed) break;
    }
}

// ---------------- kernels ----------------
__global__ void k_init_minmax() {
    g_minmax[0] = INFINITY;  g_minmax[1] = -INFINITY;
    g_minmax[2] = INFINITY;  g_minmax[3] = -INFINITY;
}

// Row L2-normalize (XLA warp row-reduce replica; bit-load-bearing)
__global__ void __launch_bounds__(256) k_norm(const float* __restrict__ x,
                                              float* __restrict__ y,
                                              int rows) {
    int warp = threadIdx.x >> 5, lane = threadIdx.x & 31;
    int r = blockIdx.x * 8 + warp;
    if (r >= rows) return;
    const float2* x2 = (const float2*)(x + (size_t)r * PD);
    float s = 0.f;
    for (int k = lane; k < PD / 2; k += 32) {
        float2 v = x2[k];
        s = __fadd_rn(s, __fmul_rn(v.x, v.x));
        s = __fadd_rn(s, __fmul_rn(v.y, v.y));
    }
    s = warpTreeSum(s);
    float den;
    if (lane == 0) den = fmaxf(sqrtf(s), 1e-12f);
    den = __shfl_sync(0xffffffffu, den, 0);
    float2* y2 = (float2*)(y + (size_t)r * PD);
    for (int k = lane; k < PD / 2; k += 32) {
        float2 v = x2[k];
        v.x = __fdiv_rn(v.x, den);
        v.y = __fdiv_rn(v.y, den);
        y2[k] = v;
    }
}

// raw[n,c] = img[n] . tn[c]  (bit-load-bearing; unchanged)
__global__ void __launch_bounds__(128) k_test() {
    int c = blockIdx.x * 128 + threadIdx.x;
    int n0 = blockIdx.y * 8;
    __shared__ float4 ish[8][PD / 4];
    const float4* imgv = (const float4*)g_img;
    for (int i = threadIdx.x; i < 8 * (PD / 4); i += 128) {
        int row = i / (PD / 4), col = i % (PD / 4);
        ish[row][col] = imgv[(size_t)(n0 + row) * (PD / 4) + col];
    }
    __syncthreads();
    if (c >= PC) return;
    float acc[8];
#pragma unroll
    for (int i = 0; i < 8; i++) acc[i] = 0.f;
    const float4* tv = (const float4*)g_tn + (size_t)c * (PD / 4);
    for (int q = 0; q < PD / 4; q++) {
        float4 t = tv[q];
#pragma unroll
        for (int i = 0; i < 8; i++) {
            float4 im = ish[i][q];
            acc[i] += t.x * im.x + t.y * im.y + t.z * im.z + t.w * im.w;
        }
    }
#pragma unroll
    for (int i = 0; i < 8; i++)
        g_raw[(size_t)(n0 + i) * PC + c] = acc[i];
}

// per-row log-softmax of x = 2*raw -> p, entropy (XLA replica; bit-load-bearing)
__global__ void __launch_bounds__(256) k_softmax() {
    int warp = threadIdx.x >> 5, lane = threadIdx.x & 31;
    int n = blockIdx.x * 8 + warp;
    if (n >= PN) return;
    const float* row = g_raw + (size_t)n * PC;

    float mx = -INFINITY;
    for (int c = lane; c < PC; c += 32) mx = fmaxf(mx, 2.0f * row[c]);
    mx = warpTreeMax(mx);
    mx = __shfl_sync(0xffffffffu, mx, 0);

    float s = 0.f;
    for (int c = lane; c < PC; c += 32)
        s = __fadd_rn(s, expf(__fsub_rn(2.0f * row[c], mx)));
    s = warpTreeSum(s);
    float lsh;
    if (lane == 0) lsh = logf(s);
    lsh = __shfl_sync(0xffffffffu, lsh, 0);

    float e = 0.f;
    for (int c = lane; c < PC; c += 32) {
        float lp = __fsub_rn(__fsub_rn(2.0f * row[c], mx), lsh);
        float p = expf(lp);
        g_p[(size_t)n * PC + c] = p;
        e = __fadd_rn(e, __fmul_rn(p, lp));
    }
    e = warpTreeSum(e);
    if (lane == 0) g_ent[n] = e;
}

// TL[m,c] = 2 * (S[:,m] . tn[c,:])  [M,C] GEMM, K=512.
// 128(m) x 64(c) tile, 8m x 4c per thread, BK=8, double-buffered.
// 2000 blocks (vs 1000) -> near-full tail wave. Per-output k-chain
// (ascending d, BK=8 tiles ascending) identical to previous -> bit-identical.
__global__ void __launch_bounds__(256) k_trainTL(const float* __restrict__ S) {
    int m0 = blockIdx.x * 128;
    int c0 = blockIdx.y * 64;
    int tx = threadIdx.x & 15;   // m dir (8 each -> 128)
    int ty = threadIdx.x >> 4;   // c dir (4 each -> 64)
    __shared__ float Ssh[2][8][128];
    __shared__ float Tsh[2][8][64];

    float acc[8][4];
#pragma unroll
    for (int i = 0; i < 8; i++)
#pragma unroll
        for (int j = 0; j < 4; j++) acc[i][j] = 0.f;

    // loader lanes
    int sk  = threadIdx.x >> 5;          // 0..7 (k)
    int smm = (threadIdx.x & 31) * 4;    // 0..124 (m)
    int tcc = threadIdx.x >> 2;          // 0..63 (c)
    int tkq = (threadIdx.x & 3) * 2;     // 0,2,4,6 (k)
    int tc  = c0 + tcc;
    bool tcv = (tc < PC);

    {
        float4 v = *(const float4*)(S + (size_t)sk * PM + m0 + smm);
        *(float4*)&Ssh[0][sk][smm] = v;
        float2 t = make_float2(0.f, 0.f);
        if (tcv) t = *(const float2*)(g_tn + (size_t)tc * PD + tkq);
        Tsh[0][tkq + 0][tcc] = t.x; Tsh[0][tkq + 1][tcc] = t.y;
    }
    __syncthreads();

    const int NT = PD / 8;  // 64
    for (int tile = 0; tile < NT; tile++) {
        int cur = tile & 1;
        bool more = (tile + 1 < NT);
        float4 pv; float2 pt;
        if (more) {
            int d0 = (tile + 1) * 8;
            pv = *(const float4*)(S + (size_t)(d0 + sk) * PM + m0 + smm);
            pt = make_float2(0.f, 0.f);
            if (tcv) pt = *(const float2*)(g_tn + (size_t)tc * PD + d0 + tkq);
        }
#pragma unroll
        for (int k = 0; k < 8; k++) {
            float av[8], bv[4];
            *(float4*)&av[0] = *(const float4*)&Ssh[cur][k][tx * 8];
            *(float4*)&av[4] = *(const float4*)&Ssh[cur][k][tx * 8 + 4];
            *(float4*)&bv[0] = *(const float4*)&Tsh[cur][k][ty * 4];
#pragma unroll
            for (int i = 0; i < 8; i++)
#pragma unroll
                for (int j = 0; j < 4; j++) acc[i][j] += av[i] * bv[j];
        }
        if (more) {
            int nxt = cur ^ 1;
            *(float4*)&Ssh[nxt][sk][smm] = pv;
            Tsh[nxt][tkq + 0][tcc] = pt.x; Tsh[nxt][tkq + 1][tcc] = pt.y;
        }
        __syncthreads();
    }

    // store: per m-row a float4 of c values (same 4-aligned guard as before)
    int c = c0 + ty * 4;
    if (c + 3 < PC) {
#pragma unroll
        for (int i = 0; i < 8; i++) {
            int m = m0 + tx * 8 + i;
            float4 o = make_float4(2.0f * acc[i][0], 2.0f * acc[i][1],
                                   2.0f * acc[i][2], 2.0f * acc[i][3]);
            *(float4*)(g_TL + (size_t)m * PC + c) = o;
        }
    }
}

// per m: mx, lsh (XLA warp row-reduce replica; bit-load-bearing)
__global__ void __launch_bounds__(256) k_trainlse() {
    int warp = threadIdx.x >> 5, lane = threadIdx.x & 31;
    int m = blockIdx.x * 8 + warp;
    if (m >= PM) return;
    const float* row = g_TL + (size_t)m * PC;
    float mx = -INFINITY;
    for (int c = lane; c < PC; c += 32) mx = fmaxf(mx, row[c]);
    mx = warpTreeMax(mx);
    mx = __shfl_sync(0xffffffffu, mx, 0);
    float s = 0.f;
    for (int c = lane; c < PC; c += 32)
        s = __fadd_rn(s, expf(__fsub_rn(row[c], mx)));
    s = warpTreeSum(s);
    if (lane == 0) {
        g_mx[m] = mx;
        g_lsh[m] = logf(s);
    }
}

// kl[n,m] = ent_n - sum_c p[n,c] * ((TL[m,c]-mx_m)-lsh_m)   K=1000
// R11 version: 64x64 tile, 4x4/thread, BK=16, double-buffered, 64-c flush.
// FROZEN (bit-load-bearing).
__global__ void __launch_bounds__(256) k_kl() {
    int m0 = blockIdx.x * 64;
    int n0 = blockIdx.y * 64;
    int tx = threadIdx.x & 15, ty = threadIdx.x >> 4;  // tx: m dir, ty: n dir
    __shared__ float Lsh[2][16][64];   // logq tile [c][m]
    __shared__ float Psh[2][16][64];   // p tile    [c][n]
    __shared__ float mxs[64], lss[64], ents[64];
    if (threadIdx.x < 64) {
        mxs[threadIdx.x] = g_mx[m0 + threadIdx.x];
        lss[threadIdx.x] = g_lsh[m0 + threadIdx.x];
        int n = n0 + threadIdx.x;
        ents[threadIdx.x] = (n < PN) ? g_ent[n] : 0.f;
    }
    __syncthreads();

    int lmm = threadIdx.x >> 2;            // 0..63 (m or n)
    int lcq = (threadIdx.x & 3) * 4;       // 0,4,8,12 (c)
    float lmx = mxs[lmm], lls = lss[lmm];
    int ln = n0 + lmm;
    bool lnv = (ln < PN);

    float facc[4][4];
    double dacc[4][4];
#pragma unroll
    for (int i = 0; i < 4; i++)
#pragma unroll
        for (int j = 0; j < 4; j++) { facc[i][j] = 0.f; dacc[i][j] = 0.0; }

    const int NT = (PC + 15) / 16;   // 63 tiles

    {
        int c = lcq;
        if (c + 3 < PC) {
            float4 v = *(const float4*)(g_TL + (size_t)(m0 + lmm) * PC + c);
            Lsh[0][lcq + 0][lmm] = __fsub_rn(__fsub_rn(v.x, lmx), lls);
            Lsh[0][lcq + 1][lmm] = __fsub_rn(__fsub_rn(v.y, lmx), lls);
            Lsh[0][lcq + 2][lmm] = __fsub_rn(__fsub_rn(v.z, lmx), lls);
            Lsh[0][lcq + 3][lmm] = __fsub_rn(__fsub_rn(v.w, lmx), lls);
        } else {
            Lsh[0][lcq + 0][lmm] = 0.f; Lsh[0][lcq + 1][lmm] = 0.f;
            Lsh[0][lcq + 2][lmm] = 0.f; Lsh[0][lcq + 3][lmm] = 0.f;
        }
        float4 p = make_float4(0.f, 0.f, 0.f, 0.f);
        if (lnv && c + 3 < PC) p = *(const float4*)(g_p + (size_t)ln * PC + c);
        Psh[0][lcq + 0][lmm] = p.x; Psh[0][lcq + 1][lmm] = p.y;
        Psh[0][lcq + 2][lmm] = p.z; Psh[0][lcq + 3][lmm] = p.w;
    }
    __syncthreads();

    int tcnt = 0;
    for (int tile = 0; tile < NT; tile++) {
        int cur = tile & 1;
        bool more = (tile + 1 < NT);
        float4 pv = make_float4(0.f, 0.f, 0.f, 0.f);
        float4 pp = make_float4(0.f, 0.f, 0.f, 0.f);
        bool pvv = false;
        if (more) {
            int c = (tile + 1) * 16 + lcq;
            pvv = (c + 3 < PC);
            if (pvv) {
                pv = *(const float4*)(g_TL + (size_t)(m0 + lmm) * PC + c);
                if (lnv) pp = *(const float4*)(g_p + (size_t)ln * PC + c);
            }
        }
#pragma unroll
        for (int k = 0; k < 16; k++) {
            float4 a = *(const float4*)&Psh[cur][k][ty * 4];
            float4 b = *(const float4*)&Lsh[cur][k][tx * 4];
            float av[4] = {a.x, a.y, a.z, a.w};
            float bv[4] = {b.x, b.y, b.z, b.w};
#pragma unroll
            for (int i = 0; i < 4; i++)
#pragma unroll
                for (int j = 0; j < 4; j++) facc[i][j] += av[i] * bv[j];
        }
        if (more) {
            int nxt = cur ^ 1;
            if (pvv) {
                Lsh[nxt][lcq + 0][lmm] = __fsub_rn(__fsub_rn(pv.x, lmx), lls);
                Lsh[nxt][lcq + 1][lmm] = __fsub_rn(__fsub_rn(pv.y, lmx), lls);
                Lsh[nxt][lcq + 2][lmm] = __fsub_rn(__fsub_rn(pv.z, lmx), lls);
                Lsh[nxt][lcq + 3][lmm] = __fsub_rn(__fsub_rn(pv.w, lmx), lls);
            } else {
                Lsh[nxt][lcq + 0][lmm] = 0.f; Lsh[nxt][lcq + 1][lmm] = 0.f;
                Lsh[nxt][lcq + 2][lmm] = 0.f; Lsh[nxt][lcq + 3][lmm] = 0.f;
            }
            Psh[nxt][lcq + 0][lmm] = pp.x; Psh[nxt][lcq + 1][lmm] = pp.y;
            Psh[nxt][lcq + 2][lmm] = pp.z; Psh[nxt][lcq + 3][lmm] = pp.w;
        }
        __syncthreads();
        if (++tcnt == 4) {
            tcnt = 0;
#pragma unroll
            for (int i = 0; i < 4; i++)
#pragma unroll
                for (int j = 0; j < 4; j++) { dacc[i][j] += facc[i][j]; facc[i][j] = 0.f; }
        }
    }
#pragma unroll
    for (int i = 0; i < 4; i++)
#pragma unroll
        for (int j = 0; j < 4; j++) dacc[i][j] += facc[i][j];

    float lmin = INFINITY, lmax = -INFINITY;
#pragma unroll
    for (int i = 0; i < 4; i++) {
        int n = n0 + ty * 4 + i;
        if (n >= PN) continue;
        float ent = ents[ty * 4 + i];
        float klv[4];
#pragma unroll
        for (int j = 0; j < 4; j++) {
            float g = (float)dacc[i][j];
            float kl = __fsub_rn(ent, g);
            klv[j] = kl;
            lmin = fminf(lmin, kl); lmax = fmaxf(lmax, kl);
        }
        size_t base = (size_t)n * PM + m0 + tx * 4;
        *(float4*)&g_kl[base] = make_float4(klv[0], klv[1], klv[2], klv[3]);
    }

    lmin = warpMinAll(lmin); lmax = warpMaxAll(lmax);
    __shared__ float r0[8], r1[8];
    int w = threadIdx.x >> 5, l = threadIdx.x & 31;
    if (l == 0) { r0[w] = lmin; r1[w] = lmax; }
    __syncthreads();
    if (threadIdx.x == 0) {
        float a = r0[0], b = r1[0];
#pragma unroll
        for (int i = 1; i < 8; i++) { a = fminf(a, r0[i]); b = fmaxf(b, r1[i]); }
        atomicMinF(&g_minmax[0], a); atomicMaxF(&g_minmax[1], b);
    }
}

// nk[n,m] = img[n] . S[:,m]   K=512, 128(m)x64(n), 8x4/thread (R11/BK=8 version)
__global__ void __launch_bounds__(256) k_nk(const float* __restrict__ S) {
    int m0 = blockIdx.x * 128;
    int n0 = blockIdx.y * 64;
    int tx = threadIdx.x & 15;   // m dir (8 each)
    int ty = threadIdx.x >> 4;   // n dir (4 each)
    __shared__ float Ssh[2][8][128];
    __shared__ float Ish[2][8][64];

    float acc[8][4];
#pragma unroll
    for (int i = 0; i < 8; i++)
#pragma unroll
        for (int j = 0; j < 4; j++) acc[i][j] = 0.f;

    int sk  = threadIdx.x >> 5;          // 0..7
    int smm = (threadIdx.x & 31) * 4;    // 0..124
    int inn = threadIdx.x >> 2;          // 0..63 (n)
    int ikq = (threadIdx.x & 3) * 2;     // 0,2,4,6 (k)
    int in_ = n0 + inn;
    bool inv = (in_ < PN);

    {
        float4 v = *(const float4*)(S + (size_t)sk * PM + m0 + smm);
        *(float4*)&Ssh[0][sk][smm] = v;
        float2 t = make_float2(0.f, 0.f);
        if (inv) t = *(const float2*)(g_img + (size_t)in_ * PD + ikq);
        Ish[0][ikq + 0][inn] = t.x; Ish[0][ikq + 1][inn] = t.y;
    }
    __syncthreads();

    const int NT = PD / 8;  // 64
    for (int tile = 0; tile < NT; tile++) {
        int cur = tile & 1;
        bool more = (tile + 1 < NT);
        float4 pv; float2 pt;
        if (more) {
            int d0 = (tile + 1) * 8;
            pv = *(const float4*)(S + (size_t)(d0 + sk) * PM + m0 + smm);
            pt = make_float2(0.f, 0.f);
            if (inv) pt = *(const float2*)(g_img + (size_t)in_ * PD + d0 + ikq);
        }
#pragma unroll
        for (int k = 0; k < 8; k++) {
            float av[8], bv[4];
            *(float4*)&av[0] = *(const float4*)&Ssh[cur][k][tx * 8];
            *(float4*)&av[4] = *(const float4*)&Ssh[cur][k][tx * 8 + 4];
            *(float4*)&bv[0] = *(const float4*)&Ish[cur][k][ty * 4];
#pragma unroll
            for (int i = 0; i < 8; i++)
#pragma unroll
                for (int j = 0; j < 4; j++) acc[i][j] += av[i] * bv[j];
        }
        if (more) {
            int nxt = cur ^ 1;
            *(float4*)&Ssh[nxt][sk][smm] = pv;
            Ish[nxt][ikq + 0][inn] = pt.x; Ish[nxt][ikq + 1][inn] = pt.y;
        }
        __syncthreads();
    }

    float nmin = INFINITY, nmax = -INFINITY;
#pragma unroll
    for (int j = 0; j < 4; j++) {
        int n = n0 + ty * 4 + j;
        if (n >= PN) continue;
        float* dst = g_nk + (size_t)n * PM + m0 + tx * 8;
#pragma unroll
        for (int i4 = 0; i4 < 8; i4 += 4) {
            float4 o = make_float4(acc[i4 + 0][j], acc[i4 + 1][j],
                                   acc[i4 + 2][j], acc[i4 + 3][j]);
            *(float4*)(dst + i4) = o;
            nmin = fminf(nmin, fminf(fminf(o.x, o.y), fminf(o.z, o.w)));
            nmax = fmaxf(nmax, fmaxf(fmaxf(o.x, o.y), fmaxf(o.z, o.w)));
        }
    }

    nmin = warpMinAll(nmin); nmax = warpMaxAll(nmax);
    __shared__ float r2[8], r3[8];
    int w = threadIdx.x >> 5, l = threadIdx.x & 31;
    if (l == 0) { r2[w] = nmin; r3[w] = nmax; }
    __syncthreads();
    if (threadIdx.x == 0) {
        float c = r2[0], d = r3[0];
#pragma unroll
        for (int i = 1; i < 8; i++) { c = fminf(c, r2[i]); d = fmaxf(d, r3[i]); }
        atomicMinF(&g_minmax[2], c); atomicMaxF(&g_minmax[3], d);
    }
}

// final: scale (ref expression order), scatter via labels, combine.
__global__ void __launch_bounds__(512) k_scatter(const int* __restrict__ labels,
                                                 float* __restrict__ out) {
    int n = blockIdx.x;
    __shared__ float skl[PC];
    __shared__ float sca[PC];
    for (int c = threadIdx.x; c < PC; c += 512) { skl[c] = 0.f; sca[c] = 0.f; }
    __syncthreads();
    float klmin = g_minmax[0], klmax = g_minmax[1];
    float nkmin = g_minmax[2], nkmax = g_minmax[3];
    float klr = __fsub_rn(klmax, klmin);
    float nkr = __fsub_rn(nkmax, nkmin);
    for (int m = threadIdx.x; m < PM; m += 512) {
        float kl = g_kl[(size_t)n * PM + m];
        float nk = g_nk[(size_t)n * PM + m];
        float y = __fdiv_rn(__fsub_rn(kl, klmin), klr);
        y = __fmul_rn(y, nkr);
        y = __fadd_rn(y, nkmin);
        float aff = -y;
        float t = __fmul_rn(BETA, nk);
        float u = __fsub_rn(BETA, t);
        float cache = expf(-u);
        int c = labels[m];
        atomicAdd(&skl[c], aff);
        atomicAdd(&sca[c], cache);
    }
    __syncthreads();
    for (int c = threadIdx.x; c < PC; c += 512) {
        float clip = __fmul_rn(100.0f, g_raw[(size_t)n * PC + c]);
        float o = __fadd_rn(clip, __fmul_rn(skl[c], GAMMA));
        o = __fadd_rn(o, __fmul_rn(sca[c], ALPHA));
        out[(size_t)n * PC + c] = o;
    }
}

// ---------------- launch ----------------
extern "C" void kernel_launch(void* const* d_in, const int* in_sizes, int n_in,
                              void* d_out, int out_size) {
    const float* image_features = (const float*)d_in[0];  // [N, D]
    const float* text_embeds    = (const float*)d_in[1];  // [C, D]
    const float* support_feats  = (const float*)d_in[2];  // [D, M]
    const int*   support_labels = (const int*)d_in[3];    // [M]
    float* out = (float*)d_out;                            // [N, C]

    float* d_tn;  cudaGetSymbolAddress((void**)&d_tn, g_tn);
    float* d_img; cudaGetSymbolAddress((void**)&d_img, g_img);

    cudaStream_t s1, s2;
    cudaStreamCreateWithFlags(&s1, cudaStreamNonBlocking);
    cudaStreamCreateWithFlags(&s2, cudaStreamNonBlocking);
    cudaEvent_t evInit, evImg, evFork, evSoft, evTL, evNk;
    cudaEventCreateWithFlags(&evInit, cudaEventDisableTiming);
    cudaEventCreateWithFlags(&evImg,  cudaEventDisableTiming);
    cudaEventCreateWithFlags(&evFork, cudaEventDisableTiming);
    cudaEventCreateWithFlags(&evSoft, cudaEventDisableTiming);
    cudaEventCreateWithFlags(&evTL,   cudaEventDisableTiming);
    cudaEventCreateWithFlags(&evNk,   cudaEventDisableTiming);

    // prologue: init on main; proper fork of s2 before using it
    k_init_minmax<<<1, 1>>>();
    cudaEventRecord(evInit, 0);
    cudaStreamWaitEvent(s2, evInit, 0);
    k_norm<<<(PN + 7) / 8, 256, 0, s2>>>(image_features, d_img, PN);
    cudaEventRecord(evImg, s2);
    k_norm<<<(PC + 7) / 8, 256>>>(text_embeds, d_tn, PC);
    cudaStreamWaitEvent(0, evImg, 0);
    cudaEventRecord(evFork, 0);

    // s1: test -> softmax (latency-bound; hides under trainTL)
    cudaStreamWaitEvent(s1, evFork, 0);
    k_test<<<dim3((PC + 127) / 128, PN / 8), 128, 0, s1>>>();
    k_softmax<<<(PN + 7) / 8, 256, 0, s1>>>();
    cudaEventRecord(evSoft, s1);

    // main: TL GEMM (128m x 64c tiles -> 2000 blocks, near-full tail wave)
    k_trainTL<<<dim3(PM / 128, (PC + 63) / 64), 256>>>(support_feats);
    cudaEventRecord(evTL, 0);

    // s2: nk GEMM after TL — FMA work runs beside MUFU/memory-bound lse
    cudaStreamWaitEvent(s2, evTL, 0);
    k_nk<<<dim3(PM / 128, (PN + 63) / 64), 256, 0, s2>>>(support_feats);
    cudaEventRecord(evNk, s2);

    // main: lse runs concurrent with nk
    k_trainlse<<<PM / 8, 256>>>();

    // main: kl needs softmax + lse (and TL, same stream)
    cudaStreamWaitEvent(0, evSoft, 0);
    k_kl<<<dim3(PM / 64, (PN + 63) / 64), 256>>>();

    // scatter needs kl + nk
    cudaStreamWaitEvent(0, evNk, 0);
    k_scatter<<<PN, 512>>>(support_labels, out);

    cudaEventDestroy(evInit); cudaEventDestroy(evImg);  cudaEventDestroy(evFork);
    cudaEventDestroy(evSoft); cudaEventDestroy(evTL);   cudaEventDestroy(evNk);
    cudaStreamDestroy(s1);
    cudaStreamDestroy(s2);
}

// round 16
// speedup vs baseline: 1.1650x; 1.1650x over previous
#include <cuda_runtime.h>
#include <math.h>

// Problem constants
#define PN 400
#define PD 512
#define PC 1000
#define PM 16000
#define ALPHA 1.0f
#define BETA 5.5f
#define GAMMA 5.0f

// ---------------- device scratch (no cudaMalloc allowed) ----------------
static __device__ float g_tn[PC * PD];         // normalized text  [C,D]
static __device__ float g_img[PN * PD];        // normalized image [N,D]
static __device__ float g_raw[PN * PC];        // raw dot img@tf  [N,C]
static __device__ float g_p[PN * PC];          // softmax probs   [N,C]
static __device__ float g_ent[PN];             // sum p log p per row
static __device__ float g_TL[(size_t)PM * PC]; // train logits [M,C] (=2*dot)
static __device__ float g_mx[PM];              // row max of TL
static __device__ float g_lsh[PM];             // log sum exp(TL - mx)
static __device__ float g_kl[(size_t)PN * PM];
static __device__ float g_nk[(size_t)PN * PM];
static __device__ float g_minmax[4];           // klmin, klmax, nkmin, nkmax

// ---------------- helpers ----------------
// XLA-GPU-style warp tree reduce (bit-load-bearing: do not change).
__device__ __forceinline__ float warpTreeSum(float v) {
#pragma unroll
    for (int o = 16; o; o >>= 1)
        v = __fadd_rn(v, __shfl_down_sync(0xffffffffu, v, o));
    return v;
}
__device__ __forceinline__ float warpTreeMax(float v) {
#pragma unroll
    for (int o = 16; o; o >>= 1)
        v = fmaxf(v, __shfl_down_sync(0xffffffffu, v, o));
    return v;
}
__device__ __forceinline__ float warpMaxAll(float v) {
#pragma unroll
    for (int o = 16; o; o >>= 1) v = fmaxf(v, __shfl_xor_sync(0xffffffffu, v, o));
    return v;
}
__device__ __forceinline__ float warpMinAll(float v) {
#pragma unroll
    for (int o = 16; o; o >>= 1) v = fminf(v, __shfl_xor_sync(0xffffffffu, v, o));
    return v;
}
__device__ void atomicMaxF(float* address, float val) {
    int* ai = (int*)address;
    int old = *ai;
    while (__int_as_float(old) < val) {
        int assumed = old;
        old = atomicCAS(ai, assumed, __float_as_int(val));
        if (old == assumed) break;
    }
}
__device__ void atomicMinF(float* address, float val) {
    int* ai = (int*)address;
    int old = *ai;
    while (__int_as_float(old) > val) {
        int assumed = old;
        old = atomicCAS(ai, assumed, __float_as_int(val));
        if (old == assumed) break;
    }
}

// ---------------- kernels ----------------
__global__ void k_init_minmax() {
    g_minmax[0] = INFINITY;  g_minmax[1] = -INFINITY;
    g_minmax[2] = INFINITY;  g_minmax[3] = -INFINITY;
}

// Row L2-normalize (XLA warp row-reduce replica; bit-load-bearing)
__global__ void __launch_bounds__(256) k_norm(const float* __restrict__ x,
                                              float* __restrict__ y,
                                              int rows) {
    int warp = threadIdx.x >> 5, lane = threadIdx.x & 31;
    int r = blockIdx.x * 8 + warp;
    if (r >= rows) return;
    const float2* x2 = (const float2*)(x + (size_t)r * PD);
    float s = 0.f;
    for (int k = lane; k < PD / 2; k += 32) {
        float2 v = x2[k];
        s = __fadd_rn(s, __fmul_rn(v.x, v.x));
        s = __fadd_rn(s, __fmul_rn(v.y, v.y));
    }
    s = warpTreeSum(s);
    float den;
    if (lane == 0) den = fmaxf(sqrtf(s), 1e-12f);
    den = __shfl_sync(0xffffffffu, den, 0);
    float2* y2 = (float2*)(y + (size_t)r * PD);
    for (int k = lane; k < PD / 2; k += 32) {
        float2 v = x2[k];
        v.x = __fdiv_rn(v.x, den);
        v.y = __fdiv_rn(v.y, den);
        y2[k] = v;
    }
}

// raw[n,c] = img[n] . tn[c]  (bit-load-bearing; unchanged)
__global__ void __launch_bounds__(128) k_test() {
    int c = blockIdx.x * 128 + threadIdx.x;
    int n0 = blockIdx.y * 8;
    __shared__ float4 ish[8][PD / 4];
    const float4* imgv = (const float4*)g_img;
    for (int i = threadIdx.x; i < 8 * (PD / 4); i += 128) {
        int row = i / (PD / 4), col = i % (PD / 4);
        ish[row][col] = imgv[(size_t)(n0 + row) * (PD / 4) + col];
    }
    __syncthreads();
    if (c >= PC) return;
    float acc[8];
#pragma unroll
    for (int i = 0; i < 8; i++) acc[i] = 0.f;
    const float4* tv = (const float4*)g_tn + (size_t)c * (PD / 4);
    for (int q = 0; q < PD / 4; q++) {
        float4 t = tv[q];
#pragma unroll
        for (int i = 0; i < 8; i++) {
            float4 im = ish[i][q];
            acc[i] += t.x * im.x + t.y * im.y + t.z * im.z + t.w * im.w;
        }
    }
#pragma unroll
    for (int i = 0; i < 8; i++)
        g_raw[(size_t)(n0 + i) * PC + c] = acc[i];
}

// per-row log-softmax of x = 2*raw -> p, entropy (XLA replica; bit-load-bearing)
__global__ void __launch_bounds__(256) k_softmax() {
    int warp = threadIdx.x >> 5, lane = threadIdx.x & 31;
    int n = blockIdx.x * 8 + warp;
    if (n >= PN) return;
    const float* row = g_raw + (size_t)n * PC;

    float mx = -INFINITY;
    for (int c = lane; c < PC; c += 32) mx = fmaxf(mx, 2.0f * row[c]);
    mx = warpTreeMax(mx);
    mx = __shfl_sync(0xffffffffu, mx, 0);

    float s = 0.f;
    for (int c = lane; c < PC; c += 32)
        s = __fadd_rn(s, expf(__fsub_rn(2.0f * row[c], mx)));
    s = warpTreeSum(s);
    float lsh;
    if (lane == 0) lsh = logf(s);
    lsh = __shfl_sync(0xffffffffu, lsh, 0);

    float e = 0.f;
    for (int c = lane; c < PC; c += 32) {
        float lp = __fsub_rn(__fsub_rn(2.0f * row[c], mx), lsh);
        float p = expf(lp);
        g_p[(size_t)n * PC + c] = p;
        e = __fadd_rn(e, __fmul_rn(p, lp));
    }
    e = warpTreeSum(e);
    if (lane == 0) g_ent[n] = e;
}

// TL[m,c] = 2 * (S[:,m] . tn[c,:])  [M,C] GEMM, K=512.
// 128x128 tile, 8x8/thread, BK=8, double-buffered (proven best shape).
__global__ void __launch_bounds__(256) k_trainTL(const float* __restrict__ S) {
    int m0 = blockIdx.x * 128;
    int c0 = blockIdx.y * 128;
    int tx = threadIdx.x & 15;   // c dir (8 each)
    int ty = threadIdx.x >> 4;   // m dir (8 each)
    __shared__ float Ssh[2][8][128];
    __shared__ float Tsh[2][8][128];

    float acc[8][8];
#pragma unroll
    for (int i = 0; i < 8; i++)
#pragma unroll
        for (int j = 0; j < 8; j++) acc[i][j] = 0.f;

    int sk  = threadIdx.x >> 5;          // 0..7 (k)
    int smm = (threadIdx.x & 31) * 4;    // 0..124 (m)
    int tcc = threadIdx.x >> 1;          // 0..127 (c)
    int tkq = (threadIdx.x & 1) * 4;     // 0 or 4 (k)
    int tc  = c0 + tcc;
    bool tcv = (tc < PC);

    {
        float4 v = *(const float4*)(S + (size_t)sk * PM + m0 + smm);
        *(float4*)&Ssh[0][sk][smm] = v;
        float4 t = make_float4(0.f, 0.f, 0.f, 0.f);
        if (tcv) t = *(const float4*)(g_tn + (size_t)tc * PD + tkq);
        Tsh[0][tkq + 0][tcc] = t.x; Tsh[0][tkq + 1][tcc] = t.y;
        Tsh[0][tkq + 2][tcc] = t.z; Tsh[0][tkq + 3][tcc] = t.w;
    }
    __syncthreads();

    const int NT = PD / 8;  // 64
    for (int tile = 0; tile < NT; tile++) {
        int cur = tile & 1;
        float4 pv, pt;
        bool more = (tile + 1 < NT);
        if (more) {
            int d0 = (tile + 1) * 8;
            pv = *(const float4*)(S + (size_t)(d0 + sk) * PM + m0 + smm);
            pt = make_float4(0.f, 0.f, 0.f, 0.f);
            if (tcv) pt = *(const float4*)(g_tn + (size_t)tc * PD + d0 + tkq);
        }
#pragma unroll
        for (int k = 0; k < 8; k++) {
            float av[8], bv[8];
            *(float4*)&av[0] = *(const float4*)&Ssh[cur][k][ty * 8];
            *(float4*)&av[4] = *(const float4*)&Ssh[cur][k][ty * 8 + 4];
            *(float4*)&bv[0] = *(const float4*)&Tsh[cur][k][tx * 8];
            *(float4*)&bv[4] = *(const float4*)&Tsh[cur][k][tx * 8 + 4];
#pragma unroll
            for (int i = 0; i < 8; i++)
#pragma unroll
                for (int j = 0; j < 8; j++) acc[i][j] += av[i] * bv[j];
        }
        if (more) {
            int nxt = cur ^ 1;
            *(float4*)&Ssh[nxt][sk][smm] = pv;
            Tsh[nxt][tkq + 0][tcc] = pt.x; Tsh[nxt][tkq + 1][tcc] = pt.y;
            Tsh[nxt][tkq + 2][tcc] = pt.z; Tsh[nxt][tkq + 3][tcc] = pt.w;
        }
        __syncthreads();
    }

#pragma unroll
    for (int i = 0; i < 8; i++) {
        int m = m0 + ty * 8 + i;
#pragma unroll
        for (int j4 = 0; j4 < 8; j4 += 4) {
            int c = c0 + tx * 8 + j4;
            if (c + 3 < PC) {
                float4 o = make_float4(2.0f * acc[i][j4 + 0], 2.0f * acc[i][j4 + 1],
                                       2.0f * acc[i][j4 + 2], 2.0f * acc[i][j4 + 3]);
                *(float4*)(g_TL + (size_t)m * PC + c) = o;
            }
        }
    }
}

// per m: mx, lsh (XLA warp row-reduce replica; bit-load-bearing)
__global__ void __launch_bounds__(256) k_trainlse() {
    int warp = threadIdx.x >> 5, lane = threadIdx.x & 31;
    int m = blockIdx.x * 8 + warp;
    if (m >= PM) return;
    const float* row = g_TL + (size_t)m * PC;
    float mx = -INFINITY;
    for (int c = lane; c < PC; c += 32) mx = fmaxf(mx, row[c]);
    mx = warpTreeMax(mx);
    mx = __shfl_sync(0xffffffffu, mx, 0);
    float s = 0.f;
    for (int c = lane; c < PC; c += 32)
        s = __fadd_rn(s, expf(__fsub_rn(row[c], mx)));
    s = warpTreeSum(s);
    if (lane == 0) {
        g_mx[m] = mx;
        g_lsh[m] = logf(s);
    }
}

// kl[n,m] = ent_n - sum_c p[n,c] * ((TL[m,c]-mx_m)-lsh_m)   K=1000
// 64x64 tile, 4x4/thread, BK=16, double-buffered, 64-c double-flush (frozen).
__global__ void __launch_bounds__(256) k_kl() {
    int m0 = blockIdx.x * 64;
    int n0 = blockIdx.y * 64;
    int tx = threadIdx.x & 15, ty = threadIdx.x >> 4;  // tx: m dir, ty: n dir
    __shared__ float Lsh[2][16][64];   // logq tile [c][m]
    __shared__ float Psh[2][16][64];   // p tile    [c][n]
    __shared__ float mxs[64], lss[64], ents[64];
    if (threadIdx.x < 64) {
        mxs[threadIdx.x] = g_mx[m0 + threadIdx.x];
        lss[threadIdx.x] = g_lsh[m0 + threadIdx.x];
        int n = n0 + threadIdx.x;
        ents[threadIdx.x] = (n < PN) ? g_ent[n] : 0.f;
    }
    __syncthreads();

    int lmm = threadIdx.x >> 2;            // 0..63 (m or n)
    int lcq = (threadIdx.x & 3) * 4;       // 0,4,8,12 (c)
    float lmx = mxs[lmm], lls = lss[lmm];
    int ln = n0 + lmm;
    bool lnv = (ln < PN);

    float facc[4][4];
    double dacc[4][4];
#pragma unroll
    for (int i = 0; i < 4; i++)
#pragma unroll
        for (int j = 0; j < 4; j++) { facc[i][j] = 0.f; dacc[i][j] = 0.0; }

    const int NT = (PC + 15) / 16;   // 63 tiles

    {
        int c = lcq;
        if (c + 3 < PC) {
            float4 v = *(const float4*)(g_TL + (size_t)(m0 + lmm) * PC + c);
            Lsh[0][lcq + 0][lmm] = __fsub_rn(__fsub_rn(v.x, lmx), lls);
            Lsh[0][lcq + 1][lmm] = __fsub_rn(__fsub_rn(v.y, lmx), lls);
            Lsh[0][lcq + 2][lmm] = __fsub_rn(__fsub_rn(v.z, lmx), lls);
            Lsh[0][lcq + 3][lmm] = __fsub_rn(__fsub_rn(v.w, lmx), lls);
        } else {
            Lsh[0][lcq + 0][lmm] = 0.f; Lsh[0][lcq + 1][lmm] = 0.f;
            Lsh[0][lcq + 2][lmm] = 0.f; Lsh[0][lcq + 3][lmm] = 0.f;
        }
        float4 p = make_float4(0.f, 0.f, 0.f, 0.f);
        if (lnv && c + 3 < PC) p = *(const float4*)(g_p + (size_t)ln * PC + c);
        Psh[0][lcq + 0][lmm] = p.x; Psh[0][lcq + 1][lmm] = p.y;
        Psh[0][lcq + 2][lmm] = p.z; Psh[0][lcq + 3][lmm] = p.w;
    }
    __syncthreads();

    int tcnt = 0;
    for (int tile = 0; tile < NT; tile++) {
        int cur = tile & 1;
        bool more = (tile + 1 < NT);
        float4 pv = make_float4(0.f, 0.f, 0.f, 0.f);
        float4 pp = make_float4(0.f, 0.f, 0.f, 0.f);
        bool pvv = false;
        if (more) {
            int c = (tile + 1) * 16 + lcq;
            pvv = (c + 3 < PC);
            if (pvv) {
                pv = *(const float4*)(g_TL + (size_t)(m0 + lmm) * PC + c);
                if (lnv) pp = *(const float4*)(g_p + (size_t)ln * PC + c);
            }
        }
#pragma unroll
        for (int k = 0; k < 16; k++) {
            float4 a = *(const float4*)&Psh[cur][k][ty * 4];
            float4 b = *(const float4*)&Lsh[cur][k][tx * 4];
            float av[4] = {a.x, a.y, a.z, a.w};
            float bv[4] = {b.x, b.y, b.z, b.w};
#pragma unroll
            for (int i = 0; i < 4; i++)
#pragma unroll
                for (int j = 0; j < 4; j++) facc[i][j] += av[i] * bv[j];
        }
        if (more) {
            int nxt = cur ^ 1;
            if (pvv) {
                Lsh[nxt][lcq + 0][lmm] = __fsub_rn(__fsub_rn(pv.x, lmx), lls);
                Lsh[nxt][lcq + 1][lmm] = __fsub_rn(__fsub_rn(pv.y, lmx), lls);
                Lsh[nxt][lcq + 2][lmm] = __fsub_rn(__fsub_rn(pv.z, lmx), lls);
                Lsh[nxt][lcq + 3][lmm] = __fsub_rn(__fsub_rn(pv.w, lmx), lls);
            } else {
                Lsh[nxt][lcq + 0][lmm] = 0.f; Lsh[nxt][lcq + 1][lmm] = 0.f;
                Lsh[nxt][lcq + 2][lmm] = 0.f; Lsh[nxt][lcq + 3][lmm] = 0.f;
            }
            Psh[nxt][lcq + 0][lmm] = pp.x; Psh[nxt][lcq + 1][lmm] = pp.y;
            Psh[nxt][lcq + 2][lmm] = pp.z; Psh[nxt][lcq + 3][lmm] = pp.w;
        }
        __syncthreads();
        if (++tcnt == 4) {
            tcnt = 0;
#pragma unroll
            for (int i = 0; i < 4; i++)
#pragma unroll
                for (int j = 0; j < 4; j++) { dacc[i][j] += facc[i][j]; facc[i][j] = 0.f; }
        }
    }
#pragma unroll
    for (int i = 0; i < 4; i++)
#pragma unroll
        for (int j = 0; j < 4; j++) dacc[i][j] += facc[i][j];

    float lmin = INFINITY, lmax = -INFINITY;
#pragma unroll
    for (int i = 0; i < 4; i++) {
        int n = n0 + ty * 4 + i;
        if (n >= PN) continue;
        float ent = ents[ty * 4 + i];
        float klv[4];
#pragma unroll
        for (int j = 0; j < 4; j++) {
            float g = (float)dacc[i][j];
            float kl = __fsub_rn(ent, g);
            klv[j] = kl;
            lmin = fminf(lmin, kl); lmax = fmaxf(lmax, kl);
        }
        size_t base = (size_t)n * PM + m0 + tx * 4;
        *(float4*)&g_kl[base] = make_float4(klv[0], klv[1], klv[2], klv[3]);
    }

    lmin = warpMinAll(lmin); lmax = warpMaxAll(lmax);
    __shared__ float r0[8], r1[8];
    int w = threadIdx.x >> 5, l = threadIdx.x & 31;
    if (l == 0) { r0[w] = lmin; r1[w] = lmax; }
    __syncthreads();
    if (threadIdx.x == 0) {
        float a = r0[0], b = r1[0];
#pragma unroll
        for (int i = 1; i < 8; i++) { a = fminf(a, r0[i]); b = fmaxf(b, r1[i]); }
        atomicMinF(&g_minmax[0], a); atomicMaxF(&g_minmax[1], b);
    }
}

// nk[n,m] = img[n] . S[:,m]   K=512, 128(m)x64(n), 8x4/thread, BK=8
__global__ void __launch_bounds__(256) k_nk(const float* __restrict__ S) {
    int m0 = blockIdx.x * 128;
    int n0 = blockIdx.y * 64;
    int tx = threadIdx.x & 15;   // m dir (8 each)
    int ty = threadIdx.x >> 4;   // n dir (4 each)
    __shared__ float Ssh[2][8][128];
    __shared__ float Ish[2][8][64];

    float acc[8][4];
#pragma unroll
    for (int i = 0; i < 8; i++)
#pragma unroll
        for (int j = 0; j < 4; j++) acc[i][j] = 0.f;

    int sk  = threadIdx.x >> 5;          // 0..7
    int smm = (threadIdx.x & 31) * 4;    // 0..124
    int inn = threadIdx.x >> 2;          // 0..63 (n)
    int ikq = (threadIdx.x & 3) * 2;     // 0,2,4,6 (k)
    int in_ = n0 + inn;
    bool inv = (in_ < PN);

    {
        float4 v = *(const float4*)(S + (size_t)sk * PM + m0 + smm);
        *(float4*)&Ssh[0][sk][smm] = v;
        float2 t = make_float2(0.f, 0.f);
        if (inv) t = *(const float2*)(g_img + (size_t)in_ * PD + ikq);
        Ish[0][ikq + 0][inn] = t.x; Ish[0][ikq + 1][inn] = t.y;
    }
    __syncthreads();

    const int NT = PD / 8;  // 64
    for (int tile = 0; tile < NT; tile++) {
        int cur = tile & 1;
        bool more = (tile + 1 < NT);
        float4 pv; float2 pt;
        if (more) {
            int d0 = (tile + 1) * 8;
            pv = *(const float4*)(S + (size_t)(d0 + sk) * PM + m0 + smm);
            pt = make_float2(0.f, 0.f);
            if (inv) pt = *(const float2*)(g_img + (size_t)in_ * PD + d0 + ikq);
        }
#pragma unroll
        for (int k = 0; k < 8; k++) {
            float av[8], bv[4];
            *(float4*)&av[0] = *(const float4*)&Ssh[cur][k][tx * 8];
            *(float4*)&av[4] = *(const float4*)&Ssh[cur][k][tx * 8 + 4];
            *(float4*)&bv[0] = *(const float4*)&Ish[cur][k][ty * 4];
#pragma unroll
            for (int i = 0; i < 8; i++)
#pragma unroll
                for (int j = 0; j < 4; j++) acc[i][j] += av[i] * bv[j];
        }
        if (more) {
            int nxt = cur ^ 1;
            *(float4*)&Ssh[nxt][sk][smm] = pv;
            Ish[nxt][ikq + 0][inn] = pt.x; Ish[nxt][ikq + 1][inn] = pt.y;
        }
        __syncthreads();
    }

    float nmin = INFINITY, nmax = -INFINITY;
#pragma unroll
    for (int j = 0; j < 4; j++) {
        int n = n0 + ty * 4 + j;
        if (n >= PN) continue;
        float* dst = g_nk + (size_t)n * PM + m0 + tx * 8;
#pragma unroll
        for (int i4 = 0; i4 < 8; i4 += 4) {
            float4 o = make_float4(acc[i4 + 0][j], acc[i4 + 1][j],
                                   acc[i4 + 2][j], acc[i4 + 3][j]);
            *(float4*)(dst + i4) = o;
            nmin = fminf(nmin, fminf(fminf(o.x, o.y), fminf(o.z, o.w)));
            nmax = fmaxf(nmax, fmaxf(fmaxf(o.x, o.y), fmaxf(o.z, o.w)));
        }
    }

    nmin = warpMinAll(nmin); nmax = warpMaxAll(nmax);
    __shared__ float r2[8], r3[8];
    int w = threadIdx.x >> 5, l = threadIdx.x & 31;
    if (l == 0) { r2[w] = nmin; r3[w] = nmax; }
    __syncthreads();
    if (threadIdx.x == 0) {
        float c = r2[0], d = r3[0];
#pragma unroll
        for (int i = 1; i < 8; i++) { c = fminf(c, r2[i]); d = fmaxf(d, r3[i]); }
        atomicMinF(&g_minmax[2], c); atomicMaxF(&g_minmax[3], d);
    }
}

// final: scale (ref expression order), scatter via labels, combine.
__global__ void __launch_bounds__(512) k_scatter(const int* __restrict__ labels,
                                                 float* __restrict__ out) {
    int n = blockIdx.x;
    __shared__ float skl[PC];
    __shared__ float sca[PC];
    for (int c = threadIdx.x; c < PC; c += 512) { skl[c] = 0.f; sca[c] = 0.f; }
    __syncthreads();
    float klmin = g_minmax[0], klmax = g_minmax[1];
    float nkmin = g_minmax[2], nkmax = g_minmax[3];
    float klr = __fsub_rn(klmax, klmin);
    float nkr = __fsub_rn(nkmax, nkmin);
    for (int m = threadIdx.x; m < PM; m += 512) {
        float kl = g_kl[(size_t)n * PM + m];
        float nk = g_nk[(size_t)n * PM + m];
        float y = __fdiv_rn(__fsub_rn(kl, klmin), klr);
        y = __fmul_rn(y, nkr);
        y = __fadd_rn(y, nkmin);
        float aff = -y;
        float t = __fmul_rn(BETA, nk);
        float u = __fsub_rn(BETA, t);
        float cache = expf(-u);
        int c = labels[m];
        atomicAdd(&skl[c], aff);
        atomicAdd(&sca[c], cache);
    }
    __syncthreads();
    for (int c = threadIdx.x; c < PC; c += 512) {
        float clip = __fmul_rn(100.0f, g_raw[(size_t)n * PC + c]);
        float o = __fadd_rn(clip, __fmul_rn(skl[c], GAMMA));
        o = __fadd_rn(o, __fmul_rn(sca[c], ALPHA));
        out[(size_t)n * PC + c] = o;
    }
}

// ---------------- launch ----------------
extern "C" void kernel_launch(void* const* d_in, const int* in_sizes, int n_in,
                              void* d_out, int out_size) {
    const float* image_features = (const float*)d_in[0];  // [N, D]
    const float* text_embeds    = (const float*)d_in[1];  // [C, D]
    const float* support_feats  = (const float*)d_in[2];  // [D, M]
    const int*   support_labels = (const int*)d_in[3];    // [M]
    float* out = (float*)d_out;                            // [N, C]

    float* d_tn;  cudaGetSymbolAddress((void**)&d_tn, g_tn);
    float* d_img; cudaGetSymbolAddress((void**)&d_img, g_img);

    cudaStream_t s1, s2;
    cudaStreamCreateWithFlags(&s1, cudaStreamNonBlocking);
    cudaStreamCreateWithFlags(&s2, cudaStreamNonBlocking);
    cudaEvent_t evFork, evSoft, evTL, evNk, evLse;
    cudaEventCreateWithFlags(&evFork, cudaEventDisableTiming);
    cudaEventCreateWithFlags(&evSoft, cudaEventDisableTiming);
    cudaEventCreateWithFlags(&evTL,   cudaEventDisableTiming);
    cudaEventCreateWithFlags(&evNk,   cudaEventDisableTiming);
    cudaEventCreateWithFlags(&evLse,  cudaEventDisableTiming);

    // main: init + norms
    k_init_minmax<<<1, 1>>>();
    k_norm<<<(PC + 7) / 8, 256>>>(text_embeds, d_tn, PC);
    k_norm<<<(PN + 7) / 8, 256>>>(image_features, d_img, PN);
    cudaEventRecord(evFork, 0);

    // s1: test -> softmax (latency-bound; hides under trainTL)
    cudaStreamWaitEvent(s1, evFork, 0);
    k_test<<<dim3((PC + 127) / 128, PN / 8), 128, 0, s1>>>();
    k_softmax<<<(PN + 7) / 8, 256, 0, s1>>>();
    cudaEventRecord(evSoft, s1);

    // main: TL GEMM
    k_trainTL<<<dim3(PM / 128, (PC + 127) / 128), 256>>>(support_feats);
    cudaEventRecord(evTL, 0);

    // s2: nk GEMM after TL — FMA work runs beside MUFU/memory-bound lse
    cudaStreamWaitEvent(s2, evTL, 0);
    k_nk<<<dim3(PM / 128, (PN + 63) / 64), 256, 0, s2>>>(support_feats);
    cudaEventRecord(evNk, s2);

    // main: lse runs concurrent with nk
    k_trainlse<<<PM / 8, 256>>>();
    cudaEventRecord(evLse, 0);

    // main: kl needs softmax + lse (and TL, same stream)
    cudaStreamWaitEvent(0, evSoft, 0);
    k_kl<<<dim3(PM / 64, (PN + 63) / 64), 256>>>();

    // scatter needs kl + nk
    cudaStreamWaitEvent(0, evNk, 0);
    k_scatter<<<PN, 512>>>(support_labels, out);

    cudaEventDestroy(evFork); cudaEventDestroy(evSoft); cudaEventDestroy(evTL);
    cudaEventDestroy(evNk);   cudaEventDestroy(evLse);
    cudaStreamDestroy(s1);
    cudaStreamDestroy(s2);
}